// round 5
// baseline (speedup 1.0000x reference)
#include <cuda_runtime.h>

#define BB 2
#define DD 64
#define HH 128
#define WW 128
#define NS (BB*DD)      // 128 slices
#define QPS 8           // parts per slice
#define NBLK (NS*QPS)   // 1024 blocks, 16 rows each (single resident wave @7/SM)
#define BROWS 16
#define SEGR 8          // owned rows per vertical segment (2 segments x 128 cols)
#define PAD 10
#define STRW 148        // u16 stride per shared row (128 + 2*10); 296 bytes

__device__ volatile float g_part_sum[NBLK];
__device__ volatile float g_part_cnt[NBLK];
__device__ volatile int   g_part_fg[NBLK];
__device__ unsigned int   g_done = 0;

// One block per (slice, eighth). Vertical: cap=10 bounds the dependency range,
// halos collapse to bitmask-ffs inits (exact under the cap). Smem rows hold
// f^2|b^2<<8 per pixel. Horizontal: both planes' 19-candidate windowed mins
// computed simultaneously in packed byte lanes (2 px x 2 planes per u32,
// vminu4, +-d taps pre-merged, odd taps via funnel shift). The zero plane's
// min is exactly 0, so combined = sqrt(minf+minb), minf+minb<=100 -> smem LUT.
// Finalize fused via last-block atomic counter (self-resetting, graph-safe).
__global__ __launch_bounds__(256, 7)
void edt_kernel(const float* __restrict__ yp, const float* __restrict__ yt,
                float* __restrict__ out)
{
    __shared__ unsigned short g2[BROWS][STRW];
    __shared__ float s_lut[101];
    __shared__ float wsum[8], wcnt[8];
    __shared__ int s_islast;
    __shared__ unsigned s_fgw[4];
    __shared__ int s_first[BB], s_last[BB];

    const int blk   = blockIdx.x;
    const int slice = blk >> 3;
    const int R0    = (blk & 7) * BROWS;
    const int t     = threadIdx.x;
    const int lane  = t & 31, warp = t >> 5;
    const float* yps = yp + (size_t)slice * HH * WW;
    const float* yts = yt + (size_t)slice * HH * WW;

    if (t < 101) s_lut[t] = sqrtf((float)t);
    // pad columns = 100 per byte: 100 + d^2 never beats a real d=0 candidate
    for (int i = t; i < BROWS * 2 * PAD; i += 256) {
        int r = i / (2 * PAD);
        int p = i - r * (2 * PAD);
        int c = (p < PAD) ? p : (p + WW);
        g2[r][c] = 0x6464;
    }

    // ---------------- vertical pass (2 segments x 128 columns) ----------------
    const int col = t & (WW - 1);
    const int seg = t >> 7;
    const int r0  = R0 + seg * SEGR;
    const int lr0 = seg * SEGR;

    int fg = 0;
    int df = 10, db = 10;
    if (r0 > 0) {                     // top halo: bitmask init (exact under cap)
        unsigned m = 0;
        #pragma unroll
        for (int k = 0; k < 10; k++) {
            float v = __ldg(&yps[(r0 - 10 + k) * WW + col]);
            m |= (v > 0.7f ? 1u : 0u) << (9 - k);   // bit0 = row r0-1
        }
        fg |= (m != 0);
        unsigned z = (~m) & 0x3FFu;
        df = z ? (__ffs(z) - 1) : 10;
        db = m ? (__ffs(m) - 1) : 10;
    }
    #pragma unroll
    for (int i = 0; i < SEGR; i++) {  // forward scan, packed state -> smem
        float v = __ldg(&yps[(r0 + i) * WW + col]);
        int sv = v > 0.7f;
        fg |= sv;
        df = sv ? min(df + 1, 10) : 0;    // edt(s): zeros where s==0
        db = sv ? 0 : min(db + 1, 10);    // edt(1-s): zeros where s==1
        g2[lr0 + i][col + PAD] = (unsigned short)(df | (db << 8));
    }
    df = 10; db = 10;
    {                                 // bottom halo: bitmask init
        int n = HH - (r0 + SEGR);
        if (n > 10) n = 10;
        if (n > 0) {
            unsigned m = 0;
            #pragma unroll
            for (int k = 0; k < 10; k++) {
                if (k < n) {
                    float v = __ldg(&yps[(r0 + SEGR + k) * WW + col]);
                    m |= (v > 0.7f ? 1u : 0u) << k;   // bit0 = row r0+SEGR
                }
            }
            fg |= (m != 0);
            unsigned z = (~m) & ((1u << n) - 1u);
            df = z ? (__ffs(z) - 1) : 10;
            db = m ? (__ffs(m) - 1) : 10;
        }
    }
    #pragma unroll
    for (int i = SEGR - 1; i >= 0; i--) {
        unsigned w = g2[lr0 + i][col + PAD];
        int fo = (int)(w & 255u), bo = (int)(w >> 8);
        int sv = fo > 0;
        df = sv ? min(df + 1, 10) : 0;
        db = sv ? 0 : min(db + 1, 10);
        int f = min(fo, df), b = min(bo, db);
        g2[lr0 + i][col + PAD] = (unsigned short)((f * f) | ((b * b) << 8));
    }
    int anyfg = __syncthreads_or(fg);

    // ------------- horizontal pass: warp -> 2 rows, 4 px/thread (2 pairs) -----
    float acc = 0.0f, accy = 0.0f;
    #pragma unroll
    for (int rr = 0; rr < 2; rr++) {
        const int row = warp * 2 + rr;
        const unsigned char* rowb = (const unsigned char*)&g2[row][0];
        const float4 y4 = __ldg((const float4*)(yts + (size_t)(R0 + row) * WW) + lane);
        #pragma unroll
        for (int pr = 0; pr < 2; pr++) {
            const int j = lane * 4 + pr * 2;           // even
            const int base = (j + PAD) * 2;            // 4-aligned
            unsigned W[11];
            #pragma unroll
            for (int k = 0; k < 11; k++)
                W[k] = *(const unsigned*)(rowb + (base - 20 + 4 * k));
            unsigned mn = W[5];                        // d = 0
            #pragma unroll
            for (int d = 1; d <= 9; d++) {
                const unsigned c4 = (unsigned)(d * d) * 0x01010101u;
                unsigned M;
                if ((d & 1) == 0) {                    // aligned taps
                    M = __vminu4(W[5 + d / 2], W[5 - d / 2]);
                } else {                               // odd taps: funnel-shift
                    unsigned vp = __funnelshift_r(W[(d + 9) / 2],  W[(d + 11) / 2], 16);
                    unsigned vm = __funnelshift_r(W[(9 - d) / 2],  W[(11 - d) / 2], 16);
                    M = __vminu4(vp, vm);
                }
                mn = __vminu4(mn, M + c4);
            }
            unsigned m0 = __dp4a(mn, 0x00000101u, 0u); // f+b, pixel j   (<=100)
            unsigned m1 = __dp4a(mn, 0x01010000u, 0u); // f+b, pixel j+1
            float ya = (pr == 0) ? y4.x : y4.z;
            float yb = (pr == 0) ? y4.y : y4.w;
            acc  += s_lut[m0] * ya + s_lut[m1] * yb;
            accy += ya + yb;                           // y in {0,1}: count == sum
        }
    }

    // ---------------- block reduction ----------------
    #pragma unroll
    for (int o = 16; o > 0; o >>= 1) {
        acc  += __shfl_down_sync(0xffffffffu, acc,  o);
        accy += __shfl_down_sync(0xffffffffu, accy, o);
    }
    if (lane == 0) { wsum[warp] = acc; wcnt[warp] = accy; }
    __syncthreads();
    if (t == 0) {
        float s = 0.0f, c = 0.0f;
        #pragma unroll
        for (int i = 0; i < 8; i++) { s += wsum[i]; c += wcnt[i]; }
        g_part_sum[blk] = s;
        g_part_cnt[blk] = c;
        g_part_fg[blk]  = anyfg;
        __threadfence();
        unsigned old = atomicAdd(&g_done, 1u);
        s_islast = (old == NBLK - 1u);
        if (s_islast) g_done = 0;   // self-reset for graph replay
    }
    __syncthreads();
    if (!s_islast) return;

    // ---------------- fused finalize (last block only) ----------------
    __threadfence();
    int f = 0;
    if (t < NS) {
        #pragma unroll
        for (int q = 0; q < QPS; q++) f |= g_part_fg[QPS * t + q];
    }
    unsigned bal = __ballot_sync(0xffffffffu, f != 0);
    if (t < NS && lane == 0) s_fgw[warp] = bal;
    __syncthreads();
    if (t < BB) {
        unsigned long long m = (unsigned long long)s_fgw[2 * t] |
                               ((unsigned long long)s_fgw[2 * t + 1] << 32);
        s_first[t] = m ? (__ffsll((long long)m) - 1) : 0;      // argmax(all-false)=0
        s_last[t]  = m ? (63 - __clzll((long long)m)) : (DD - 1);
    }
    __syncthreads();
    float ms = 0.0f, mc = 0.0f;
    #pragma unroll
    for (int q = 0; q < 4; q++) {
        int p  = t + q * 256;            // part index (NBLK=1024)
        int sl = p >> 3;
        int b  = sl >> 6;
        int d  = sl & (DD - 1);
        int in = (d >= s_first[b]) && (d <= s_last[b]);
        ms += in ? g_part_sum[p] : 0.0f;
        mc += g_part_cnt[p];
    }
    #pragma unroll
    for (int o = 16; o > 0; o >>= 1) {
        ms += __shfl_down_sync(0xffffffffu, ms, o);
        mc += __shfl_down_sync(0xffffffffu, mc, o);
    }
    if (lane == 0) { wsum[warp] = ms; wcnt[warp] = mc; }
    __syncthreads();
    if (t == 0) {
        float s = 0.0f, c = 0.0f;
        #pragma unroll
        for (int i = 0; i < 8; i++) { s += wsum[i]; c += wcnt[i]; }
        out[0] = s / c;
    }
}

extern "C" void kernel_launch(void* const* d_in, const int* in_sizes, int n_in,
                              void* d_out, int out_size)
{
    const float* yp = (const float*)d_in[0];
    const float* yt = (const float*)d_in[1];
    float* out = (float*)d_out;
    edt_kernel<<<NBLK, 256>>>(yp, yt, out);
}

// round 6
// speedup vs baseline: 1.1715x; 1.1715x over previous
#include <cuda_runtime.h>

#define BB 2
#define DD 64
#define HH 128
#define WW 128
#define NS (BB*DD)      // 128 slices
#define QPS 8           // parts per slice
#define NBLK (NS*QPS)   // 1024 blocks, 16 rows each (single wave @ 7 blocks/SM)
#define BROWS 16
#define SEGR 8          // owned rows per vertical segment (2 segments x 128 cols)
#define PAD 10
#define STRW 148        // u16 stride per shared row (128 + 2*10)

__device__ volatile float g_part_sum[NBLK];
__device__ volatile float g_part_cnt[NBLK];
__device__ volatile int   g_part_fg[NBLK];
__device__ unsigned int   g_done = 0;

__device__ __forceinline__ float fast_sqrt(float x) {
    float r; asm("sqrt.approx.f32 %0, %1;" : "=f"(r) : "f"(x)); return r;
}

// One block per (slice, eighth). Vertical: cap=10 bounds the dependency range;
// halos collapse to bitmask-ffs inits (exact under the cap). Smem rows hold
// f^2|b^2<<8 per pixel. Horizontal: per pixel select the nonzero plane (s is
// binary) and take a 19-candidate windowed min — with a warp-uniform EARLY
// EXIT: once mn <= d^2 for every lane, all remaining candidates (>= d^2) are
// dead, so the loop breaks exactly. Finalize fused via last-block counter.
__global__ __launch_bounds__(256, 7)
void edt_kernel(const float* __restrict__ yp, const float* __restrict__ yt,
                float* __restrict__ out)
{
    __shared__ unsigned short g2[BROWS][STRW];
    __shared__ float wsum[8], wcnt[8];
    __shared__ int s_islast;
    __shared__ unsigned s_fgw[4];
    __shared__ int s_first[BB], s_last[BB];

    const int blk   = blockIdx.x;
    const int slice = blk >> 3;
    const int R0    = (blk & 7) * BROWS;
    const int t     = threadIdx.x;
    const int lane  = t & 31, warp = t >> 5;
    const float* yps = yp + (size_t)slice * HH * WW;
    const float* yts = yt + (size_t)slice * HH * WW;

    // pad columns = 100 per byte: 100 + d^2 never beats a real d=0 candidate
    for (int i = t; i < BROWS * 2 * PAD; i += 256) {
        int r = i / (2 * PAD);
        int p = i - r * (2 * PAD);
        int c = (p < PAD) ? p : (p + WW);
        g2[r][c] = 0x6464;
    }

    // ---------------- vertical pass (2 segments x 128 columns) ----------------
    const int col = t & (WW - 1);
    const int seg = t >> 7;
    const int r0  = R0 + seg * SEGR;
    const int lr0 = seg * SEGR;

    int fg = 0;
    int df = 10, db = 10;
    if (r0 > 0) {                     // top halo: bitmask init (exact under cap)
        unsigned m = 0;
        #pragma unroll
        for (int k = 0; k < 10; k++) {
            float v = __ldg(&yps[(r0 - 10 + k) * WW + col]);
            m |= (v > 0.7f ? 1u : 0u) << (9 - k);   // bit0 = row r0-1
        }
        fg |= (m != 0);
        unsigned z = (~m) & 0x3FFu;
        df = z ? (__ffs(z) - 1) : 10;
        db = m ? (__ffs(m) - 1) : 10;
    }
    #pragma unroll
    for (int i = 0; i < SEGR; i++) {  // forward scan, packed state -> smem
        float v = __ldg(&yps[(r0 + i) * WW + col]);
        int sv = v > 0.7f;
        fg |= sv;
        df = sv ? min(df + 1, 10) : 0;    // edt(s): zeros where s==0
        db = sv ? 0 : min(db + 1, 10);    // edt(1-s): zeros where s==1
        g2[lr0 + i][col + PAD] = (unsigned short)(df | (db << 8));
    }
    df = 10; db = 10;
    {                                 // bottom halo: bitmask init
        int n = HH - (r0 + SEGR);
        if (n > 10) n = 10;
        if (n > 0) {
            unsigned m = 0;
            #pragma unroll
            for (int k = 0; k < 10; k++) {
                if (k < n) {
                    float v = __ldg(&yps[(r0 + SEGR + k) * WW + col]);
                    m |= (v > 0.7f ? 1u : 0u) << k;   // bit0 = row r0+SEGR
                }
            }
            fg |= (m != 0);
            unsigned z = (~m) & ((1u << n) - 1u);
            df = z ? (__ffs(z) - 1) : 10;
            db = m ? (__ffs(m) - 1) : 10;
        }
    }
    #pragma unroll
    for (int i = SEGR - 1; i >= 0; i--) {
        unsigned w = g2[lr0 + i][col + PAD];
        int fo = (int)(w & 255u), bo = (int)(w >> 8);
        int sv = fo > 0;
        df = sv ? min(df + 1, 10) : 0;
        db = sv ? 0 : min(db + 1, 10);
        int f = min(fo, df), b = min(bo, db);
        g2[lr0 + i][col + PAD] = (unsigned short)((f * f) | ((b * b) << 8));
    }
    int anyfg = __syncthreads_or(fg);

    // ------- horizontal pass: warp -> 2 rows, early-exit windowed min ---------
    float acc = 0.0f, accy = 0.0f;
    #pragma unroll
    for (int rr = 0; rr < 2; rr++) {
        const int row = warp * 2 + rr;
        const unsigned char* rowb = (const unsigned char*)&g2[row][0];
        const float* yrow = yts + (size_t)(R0 + row) * WW;
        #pragma unroll
        for (int m = 0; m < 4; m++) {
            const int j = lane + m * 32;
            const int base = (j + PAD) * 2;
            unsigned w = *(const unsigned short*)(rowb + base);
            int fo = (int)(w & 255u);
            const unsigned char* p = rowb + ((fo > 0) ? 0 : 1);  // nonzero plane
            int mn = (fo > 0) ? fo : (int)(w >> 8);              // d=0 candidate
            int d2 = 0;
            #pragma unroll 1
            for (int d = 1; d <= 9; d++) {
                d2 += 2 * d - 1;                                 // d*d
                if (__all_sync(0xffffffffu, mn <= d2)) break;    // exact cutoff
                mn = min(mn, (int)p[base + 2 * d] + d2);
                mn = min(mn, (int)p[base - 2 * d] + d2);
            }
            float c = fminf(fast_sqrt((float)mn), 10.0f);
            float y = __ldg(&yrow[j]);
            acc  += c * y;
            accy += y;                   // y in {0,1}: count == sum
        }
    }

    // ---------------- block reduction ----------------
    #pragma unroll
    for (int o = 16; o > 0; o >>= 1) {
        acc  += __shfl_down_sync(0xffffffffu, acc,  o);
        accy += __shfl_down_sync(0xffffffffu, accy, o);
    }
    if (lane == 0) { wsum[warp] = acc; wcnt[warp] = accy; }
    __syncthreads();
    if (t == 0) {
        float s = 0.0f, c = 0.0f;
        #pragma unroll
        for (int i = 0; i < 8; i++) { s += wsum[i]; c += wcnt[i]; }
        g_part_sum[blk] = s;
        g_part_cnt[blk] = c;
        g_part_fg[blk]  = anyfg;
        __threadfence();
        unsigned old = atomicAdd(&g_done, 1u);
        s_islast = (old == NBLK - 1u);
        if (s_islast) g_done = 0;   // self-reset for graph replay
    }
    __syncthreads();
    if (!s_islast) return;

    // ---------------- fused finalize (last block only) ----------------
    __threadfence();
    int f = 0;
    if (t < NS) {
        #pragma unroll
        for (int q = 0; q < QPS; q++) f |= g_part_fg[QPS * t + q];
    }
    unsigned bal = __ballot_sync(0xffffffffu, f != 0);
    if (t < NS && lane == 0) s_fgw[warp] = bal;
    __syncthreads();
    if (t < BB) {
        unsigned long long m = (unsigned long long)s_fgw[2 * t] |
                               ((unsigned long long)s_fgw[2 * t + 1] << 32);
        s_first[t] = m ? (__ffsll((long long)m) - 1) : 0;      // argmax(all-false)=0
        s_last[t]  = m ? (63 - __clzll((long long)m)) : (DD - 1);
    }
    __syncthreads();
    float ms = 0.0f, mc = 0.0f;
    #pragma unroll
    for (int q = 0; q < 4; q++) {
        int p  = t + q * 256;            // part index (NBLK=1024)
        int sl = p >> 3;
        int b  = sl >> 6;
        int d  = sl & (DD - 1);
        int in = (d >= s_first[b]) && (d <= s_last[b]);
        ms += in ? g_part_sum[p] : 0.0f;
        mc += g_part_cnt[p];
    }
    #pragma unroll
    for (int o = 16; o > 0; o >>= 1) {
        ms += __shfl_down_sync(0xffffffffu, ms, o);
        mc += __shfl_down_sync(0xffffffffu, mc, o);
    }
    if (lane == 0) { wsum[warp] = ms; wcnt[warp] = mc; }
    __syncthreads();
    if (t == 0) {
        float s = 0.0f, c = 0.0f;
        #pragma unroll
        for (int i = 0; i < 8; i++) { s += wsum[i]; c += wcnt[i]; }
        out[0] = s / c;
    }
}

extern "C" void kernel_launch(void* const* d_in, const int* in_sizes, int n_in,
                              void* d_out, int out_size)
{
    const float* yp = (const float*)d_in[0];
    const float* yt = (const float*)d_in[1];
    float* out = (float*)d_out;
    edt_kernel<<<NBLK, 256>>>(yp, yt, out);
}